// round 1
// baseline (speedup 1.0000x reference)
#include <cuda_runtime.h>
#include <cstdint>

typedef unsigned long long u64;

__device__ __forceinline__ u64 pack2(float a, float b) {
    u64 r; asm("mov.b64 %0, {%1, %2};" : "=l"(r) : "f"(a), "f"(b)); return r;
}
__device__ __forceinline__ void fma2(u64& acc, u64 x, u64 w) {
    asm("fma.rn.f32x2 %0, %1, %2, %0;" : "+l"(acc) : "l"(x), "l"(w));
}
__device__ __forceinline__ float2 unpack2(u64 v) {
    float2 f; asm("mov.b64 {%0, %1}, %2;" : "=f"(f.x), "=f"(f.y) : "l"(v)); return f;
}

// Static multi-resolution layout
//   levels R = 16, 32, 48, 64 ; level base offsets in N: 0, 4096, 36864, 147456
//   N_TOTAL = 409600, B = 4, Cin = Cout = 16, K = 3
// Tiling: 8x8x8 outputs per block (all R divisible by 8).
//   tiles/level/batch: 8, 64, 216, 512 -> 800 per batch -> 3200 blocks.
constexpr int N_TOTAL = 409600;
constexpr int WS_FLOATS = 27 * 16 * 16;        // 6912 (weights [tap][cin][cout])
constexpr int XS_FLOATS = 10 * 10 * 10 * 16;   // 16000 (halo tile, channels-last)
constexpr size_t SMEM_BYTES = (size_t)(WS_FLOATS + XS_FLOATS) * sizeof(float);

__global__ __launch_bounds__(256, 2)
void conv3d_ml_kernel(const float* __restrict__ in, const float* __restrict__ wgt,
                      const float* __restrict__ bias, float* __restrict__ out)
{
    extern __shared__ __align__(16) float smem[];
    float* ws = smem;                 // [tap][cin][cout] = [27][16][16]
    float* xs = smem + WS_FLOATS;     // [hz][hy][hx][c]  = [10][10][10][16]

    const int t = threadIdx.x;

    // ---- stage weights: reorder [cout][cin][tap] -> [tap][cin][cout] ----
    for (int i = t; i < WS_FLOATS; i += 256) {
        int cout = i & 15, cin = (i >> 4) & 15, tap = i >> 8;
        ws[i] = wgt[(cout * 16 + cin) * 27 + tap];
    }

    // ---- decode block -> (batch, level, tile coords) ----
    int bid = blockIdx.x;
    int b = bid / 800;
    int tl = bid - b * 800;
    int R, nbase, lt;
    if (tl < 8)        { R = 16; nbase = 0;      lt = tl;       }
    else if (tl < 72)  { R = 32; nbase = 4096;   lt = tl - 8;   }
    else if (tl < 288) { R = 48; nbase = 36864;  lt = tl - 72;  }
    else               { R = 64; nbase = 147456; lt = tl - 288; }
    const int td = R >> 3;
    const int tx = lt % td; const int tmp = lt / td;
    const int ty = tmp % td; const int tz = tmp / td;
    const int x0 = tx << 3, y0 = ty << 3, z0 = tz << 3;

    const float* inb = in + ((size_t)b * N_TOTAL + nbase) * 16;

    // ---- stage input halo tile 10x10x10 rows x 16 ch (zero outside level) ----
    for (int i = t; i < 1000 * 4; i += 256) {
        int comp = i & 3;
        int row  = i >> 2;
        int hx = row % 10; int r2 = row / 10; int hy = r2 % 10; int hz = r2 / 10;
        int gx = x0 + hx - 1, gy = y0 + hy - 1, gz = z0 + hz - 1;
        float4 v = make_float4(0.f, 0.f, 0.f, 0.f);
        if ((unsigned)gx < (unsigned)R && (unsigned)gy < (unsigned)R && (unsigned)gz < (unsigned)R) {
            v = *(const float4*)(inb + (size_t)((gz * R + gy) * R + gx) * 16 + comp * 4);
        }
        *(float4*)(xs + row * 16 + comp * 4) = v;
    }
    __syncthreads();

    // ---- compute: each thread owns 2 output voxels (z, z+1), all 16 couts ----
    const int lx = t & 7, ly = (t >> 3) & 7, lz = (t >> 6) << 1;

    u64 acc[2][8];   // [voxel][cout-pair], packed f32x2
    #pragma unroll
    for (int v = 0; v < 2; ++v)
        #pragma unroll
        for (int p = 0; p < 8; ++p) acc[v][p] = 0ull;

    #pragma unroll 1
    for (int dz = 0; dz < 3; ++dz) {
        #pragma unroll 1
        for (int dy = 0; dy < 3; ++dy) {
            #pragma unroll 1
            for (int dx = 0; dx < 3; ++dx) {
                const float* xr0 = xs + (((lz + dz) * 10 + (ly + dy)) * 10 + (lx + dx)) * 16;
                // load the two neighbor rows (16 ch each) into registers
                float xa[16], xb[16];
                #pragma unroll
                for (int q = 0; q < 4; ++q) {
                    float4 a = *(const float4*)(xr0 + q * 4);
                    float4 c = *(const float4*)(xr0 + 1600 + q * 4);  // hz+1 row
                    xa[q*4+0] = a.x; xa[q*4+1] = a.y; xa[q*4+2] = a.z; xa[q*4+3] = a.w;
                    xb[q*4+0] = c.x; xb[q*4+1] = c.y; xb[q*4+2] = c.z; xb[q*4+3] = c.w;
                }
                const float* wt = ws + ((dz * 3 + dy) * 3 + dx) * 256;
                #pragma unroll
                for (int cin = 0; cin < 16; ++cin) {
                    // 16 couts = 8 f32x2 pairs = 2 LDS.128 (uniform broadcast)
                    const ulonglong2* wp = (const ulonglong2*)(wt + cin * 16);
                    ulonglong2 w01 = wp[0];
                    ulonglong2 w23 = wp[1];
                    ulonglong2 w45 = wp[2];
                    ulonglong2 w67 = wp[3];
                    u64 xx0 = pack2(xa[cin], xa[cin]);
                    u64 xx1 = pack2(xb[cin], xb[cin]);
                    fma2(acc[0][0], xx0, w01.x); fma2(acc[1][0], xx1, w01.x);
                    fma2(acc[0][1], xx0, w01.y); fma2(acc[1][1], xx1, w01.y);
                    fma2(acc[0][2], xx0, w23.x); fma2(acc[1][2], xx1, w23.x);
                    fma2(acc[0][3], xx0, w23.y); fma2(acc[1][3], xx1, w23.y);
                    fma2(acc[0][4], xx0, w45.x); fma2(acc[1][4], xx1, w45.x);
                    fma2(acc[0][5], xx0, w45.y); fma2(acc[1][5], xx1, w45.y);
                    fma2(acc[0][6], xx0, w67.x); fma2(acc[1][6], xx1, w67.x);
                    fma2(acc[0][7], xx0, w67.y); fma2(acc[1][7], xx1, w67.y);
                }
            }
        }
    }

    // ---- epilogue: + bias, store 16 couts per voxel as 4 float4s ----
    const float4* b4 = (const float4*)bias;
    const float4 bb0 = b4[0], bb1 = b4[1], bb2 = b4[2], bb3 = b4[3];

    #pragma unroll
    for (int v = 0; v < 2; ++v) {
        const int gz = z0 + lz + v, gy = y0 + ly, gx = x0 + lx;
        const size_t n = (size_t)nbase + (size_t)(gz * R + gy) * R + gx;
        float* o = out + ((size_t)b * N_TOTAL + n) * 16;

        float2 q0 = unpack2(acc[v][0]), q1 = unpack2(acc[v][1]);
        float2 q2 = unpack2(acc[v][2]), q3 = unpack2(acc[v][3]);
        float2 q4 = unpack2(acc[v][4]), q5 = unpack2(acc[v][5]);
        float2 q6 = unpack2(acc[v][6]), q7 = unpack2(acc[v][7]);

        *(float4*)(o + 0)  = make_float4(q0.x + bb0.x, q0.y + bb0.y, q1.x + bb0.z, q1.y + bb0.w);
        *(float4*)(o + 4)  = make_float4(q2.x + bb1.x, q2.y + bb1.y, q3.x + bb1.z, q3.y + bb1.w);
        *(float4*)(o + 8)  = make_float4(q4.x + bb2.x, q4.y + bb2.y, q5.x + bb2.z, q5.y + bb2.w);
        *(float4*)(o + 12) = make_float4(q6.x + bb3.x, q6.y + bb3.y, q7.x + bb3.z, q7.y + bb3.w);
    }
}

extern "C" void kernel_launch(void* const* d_in, const int* in_sizes, int n_in,
                              void* d_out, int out_size) {
    (void)in_sizes; (void)n_in; (void)out_size;
    const float* in  = (const float*)d_in[0];
    const float* w   = (const float*)d_in[1];
    const float* bs  = (const float*)d_in[2];
    float* out = (float*)d_out;

    cudaFuncSetAttribute(conv3d_ml_kernel,
                         cudaFuncAttributeMaxDynamicSharedMemorySize, (int)SMEM_BYTES);
    conv3d_ml_kernel<<<3200, 256, SMEM_BYTES>>>(in, w, bs, out);
}

// round 2
// speedup vs baseline: 1.4329x; 1.4329x over previous
#include <cuda_runtime.h>
#include <cstdint>

typedef unsigned long long u64;

__device__ __forceinline__ u64 pack2(float a, float b) {
    u64 r; asm("mov.b64 %0, {%1, %2};" : "=l"(r) : "f"(a), "f"(b)); return r;
}
__device__ __forceinline__ void fma2(u64& acc, u64 x, u64 w) {
    asm("fma.rn.f32x2 %0, %1, %2, %0;" : "+l"(acc) : "l"(x), "l"(w));
}
__device__ __forceinline__ float2 unpack2(u64 v) {
    float2 f; asm("mov.b64 {%0, %1}, %2;" : "=f"(f.x), "=f"(f.y) : "l"(v)); return f;
}

// Static multi-resolution layout
//   levels R = 16, 32, 48, 64 ; level base offsets in N: 0, 4096, 36864, 147456
//   N_TOTAL = 409600, B = 4, Cin = Cout = 16, K = 3
// Tiling: 8x8x8 outputs per block; 128 threads; each thread owns a z-column
// of 4 voxels (weight-broadcast LDS amortized 4x vs R1).
// Smem x tile layout: [cg(4)][hz(10)][hy(10)][hx(10)] of float4 -> compute-side
// LDS.128 is conflict-free (16B lane stride along lx, ly rotates bank groups).
constexpr int N_TOTAL  = 409600;
constexpr int WS_FLOATS = 27 * 16 * 16;            // 6912: [tap][cin][cout]
constexpr int XS_F4     = 4 * 1000;                // 4 channel-groups x 10^3 rows
constexpr size_t SMEM_BYTES = (size_t)WS_FLOATS * 4 + (size_t)XS_F4 * 16; // 91648 B

__global__ __launch_bounds__(128, 2)
void conv3d_ml_kernel(const float* __restrict__ in, const float* __restrict__ wgt,
                      const float* __restrict__ bias, float* __restrict__ out)
{
    extern __shared__ __align__(16) float smem[];
    float*  ws  = smem;                          // [27][16][16]
    float4* xs4 = (float4*)(smem + WS_FLOATS);   // [cg][hz][hy][hx]

    const int t = threadIdx.x;

    // ---- stage weights: reorder [cout][cin][tap] -> [tap][cin][cout] ----
    for (int i = t; i < WS_FLOATS; i += 128) {
        int cout = i & 15, cin = (i >> 4) & 15, tap = i >> 8;
        ws[i] = wgt[(cout * 16 + cin) * 27 + tap];
    }

    // ---- decode block -> (batch, level, tile coords) ----
    int bid = blockIdx.x;
    int b = bid / 800;
    int tl = bid - b * 800;
    int R, nbase, lt;
    if (tl < 8)        { R = 16; nbase = 0;      lt = tl;       }
    else if (tl < 72)  { R = 32; nbase = 4096;   lt = tl - 8;   }
    else if (tl < 288) { R = 48; nbase = 36864;  lt = tl - 72;  }
    else               { R = 64; nbase = 147456; lt = tl - 288; }
    const int td = R >> 3;
    const int tx = lt % td; const int tmp = lt / td;
    const int ty = tmp % td; const int tz = tmp / td;
    const int x0 = tx << 3, y0 = ty << 3, z0 = tz << 3;

    const float* inb = in + ((size_t)b * N_TOTAL + nbase) * 16;

    // ---- stage halo tile 10x10x10 x 16ch into cg-major float4 layout ----
    // i -> (comp = cg, row): 4 consecutive lanes read one full 64B gmem row.
    for (int i = t; i < 4000; i += 128) {
        int comp = i & 3;
        int row  = i >> 2;
        int hx = row % 10; int r2 = row / 10; int hy = r2 % 10; int hz = r2 / 10;
        int gx = x0 + hx - 1, gy = y0 + hy - 1, gz = z0 + hz - 1;
        float4 v = make_float4(0.f, 0.f, 0.f, 0.f);
        if ((unsigned)gx < (unsigned)R && (unsigned)gy < (unsigned)R && (unsigned)gz < (unsigned)R) {
            v = *(const float4*)(inb + (size_t)((gz * R + gy) * R + gx) * 16 + comp * 4);
        }
        xs4[comp * 1000 + row] = v;
    }
    __syncthreads();

    // ---- compute: thread owns voxels (lx, ly, z0+lz .. z0+lz+3), 16 couts ----
    const int lx = t & 7, ly = (t >> 3) & 7, lz = (t >> 6) << 2;

    u64 acc[4][8];   // [voxel][cout-pair]
    #pragma unroll
    for (int v = 0; v < 4; ++v)
        #pragma unroll
        for (int p = 0; p < 8; ++p) acc[v][p] = 0ull;

    #pragma unroll 1
    for (int dy = 0; dy < 3; ++dy) {
        #pragma unroll 1
        for (int dx = 0; dx < 3; ++dx) {
            const int sb = (ly + dy) * 10 + (lx + dx);   // row index w/o hz, cg
            #pragma unroll 1
            for (int q = 0; q < 4; ++q) {                // channel group: cin = 4q..4q+3
                // load 6 z-slices of this channel group, pre-duplicated for f32x2
                u64 xp[6][4];
                #pragma unroll
                for (int s = 0; s < 6; ++s) {
                    float4 v = xs4[q * 1000 + (lz + s) * 100 + sb];
                    xp[s][0] = pack2(v.x, v.x);
                    xp[s][1] = pack2(v.y, v.y);
                    xp[s][2] = pack2(v.z, v.z);
                    xp[s][3] = pack2(v.w, v.w);
                }
                #pragma unroll
                for (int dz = 0; dz < 3; ++dz) {
                    const float* wt = ws + ((dz * 3 + dy) * 3 + dx) * 256 + q * 64;
                    #pragma unroll
                    for (int c = 0; c < 4; ++c) {
                        const ulonglong2* wp = (const ulonglong2*)(wt + c * 16);
                        ulonglong2 w01 = wp[0];
                        ulonglong2 w23 = wp[1];
                        ulonglong2 w45 = wp[2];
                        ulonglong2 w67 = wp[3];
                        #pragma unroll
                        for (int v = 0; v < 4; ++v) {
                            u64 xx = xp[dz + v][c];
                            fma2(acc[v][0], xx, w01.x);
                            fma2(acc[v][1], xx, w01.y);
                            fma2(acc[v][2], xx, w23.x);
                            fma2(acc[v][3], xx, w23.y);
                            fma2(acc[v][4], xx, w45.x);
                            fma2(acc[v][5], xx, w45.y);
                            fma2(acc[v][6], xx, w67.x);
                            fma2(acc[v][7], xx, w67.y);
                        }
                    }
                }
            }
        }
    }

    // ---- epilogue: + bias, store 16 couts per voxel as 4 float4s ----
    const float4* b4 = (const float4*)bias;
    const float4 bb0 = b4[0], bb1 = b4[1], bb2 = b4[2], bb3 = b4[3];

    #pragma unroll
    for (int v = 0; v < 4; ++v) {
        const int gz = z0 + lz + v, gy = y0 + ly, gx = x0 + lx;
        const size_t n = (size_t)nbase + (size_t)(gz * R + gy) * R + gx;
        float* o = out + ((size_t)b * N_TOTAL + n) * 16;

        float2 q0 = unpack2(acc[v][0]), q1 = unpack2(acc[v][1]);
        float2 q2 = unpack2(acc[v][2]), q3 = unpack2(acc[v][3]);
        float2 q4 = unpack2(acc[v][4]), q5 = unpack2(acc[v][5]);
        float2 q6 = unpack2(acc[v][6]), q7 = unpack2(acc[v][7]);

        *(float4*)(o + 0)  = make_float4(q0.x + bb0.x, q0.y + bb0.y, q1.x + bb0.z, q1.y + bb0.w);
        *(float4*)(o + 4)  = make_float4(q2.x + bb1.x, q2.y + bb1.y, q3.x + bb1.z, q3.y + bb1.w);
        *(float4*)(o + 8)  = make_float4(q4.x + bb2.x, q4.y + bb2.y, q5.x + bb2.z, q5.y + bb2.w);
        *(float4*)(o + 12) = make_float4(q6.x + bb3.x, q6.y + bb3.y, q7.x + bb3.z, q7.y + bb3.w);
    }
}

extern "C" void kernel_launch(void* const* d_in, const int* in_sizes, int n_in,
                              void* d_out, int out_size) {
    (void)in_sizes; (void)n_in; (void)out_size;
    const float* in  = (const float*)d_in[0];
    const float* w   = (const float*)d_in[1];
    const float* bs  = (const float*)d_in[2];
    float* out = (float*)d_out;

    cudaFuncSetAttribute(conv3d_ml_kernel,
                         cudaFuncAttributeMaxDynamicSharedMemorySize, (int)SMEM_BYTES);
    conv3d_ml_kernel<<<3200, 128, SMEM_BYTES>>>(in, w, bs, out);
}